// round 1
// baseline (speedup 1.0000x reference)
#include <cuda_runtime.h>
#include <cstdint>

// ---------------------------------------------------------------------------
// JAX RNG scheme selector:
//   1 = jax_threefry_partitionable=True  (default in JAX >= 0.5)
//   0 = legacy/original threefry counter scheme (JAX < 0.5 default)
// If rel_err comes back O(1), flip this.
// ---------------------------------------------------------------------------
#define RNG_PARTITIONABLE 1

static constexpr int Bn   = 8;
static constexpr int Cn   = 5;
static constexpr int Hn   = 512;
static constexpr int Wn   = 512;
static constexpr int FMAX = 16;
static constexpr int HW   = Hn * Wn;          // 262144
static constexpr int NPIX = Bn * HW;          // 2097152
static constexpr unsigned HALF = (unsigned)(Bn / 2) * FMAX * HW; // 16777216 (legacy pairing)

__device__ float g_bias[Bn];

// ---------------------------------------------------------------------------
// Threefry-2x32 (JAX's 20-round variant)
// ---------------------------------------------------------------------------
__device__ __forceinline__ void tf2x32(uint32_t k0, uint32_t k1,
                                       uint32_t x0, uint32_t x1,
                                       uint32_t& o0, uint32_t& o1) {
    uint32_t k2 = k0 ^ k1 ^ 0x1BD11BDAu;
    x0 += k0; x1 += k1;
#define TFR(r) { x0 += x1; x1 = __funnelshift_l(x1, x1, (r)); x1 ^= x0; }
    TFR(13) TFR(15) TFR(26) TFR(6)   x0 += k1; x1 += k2 + 1u;
    TFR(17) TFR(29) TFR(16) TFR(24)  x0 += k2; x1 += k0 + 2u;
    TFR(13) TFR(15) TFR(26) TFR(6)   x0 += k0; x1 += k1 + 3u;
    TFR(17) TFR(29) TFR(16) TFR(24)  x0 += k1; x1 += k2 + 4u;
    TFR(13) TFR(15) TFR(26) TFR(6)   x0 += k2; x1 += k0 + 5u;
#undef TFR
    o0 = x0; o1 = x1;
}

// bits -> float in [0,1): bitcast((bits>>9)|0x3f800000) - 1
__device__ __forceinline__ float bits_to_unit(uint32_t bits) {
    return __uint_as_float((bits >> 9) | 0x3f800000u) - 1.0f;
}

// ---------------------------------------------------------------------------
// Kernel 1: per-batch bias = relu(mean(input[b, 1, :, :]))
// ---------------------------------------------------------------------------
__global__ void bias_kernel(const float* __restrict__ in) {
    int b = blockIdx.x;
    const float* p = in + ((size_t)b * Cn + 1) * HW;
    float s = 0.0f;
    for (int i = threadIdx.x; i < HW; i += blockDim.x) s += p[i];
    // block reduction
    __shared__ float sm[32];
    #pragma unroll
    for (int o = 16; o > 0; o >>= 1) s += __shfl_down_sync(0xffffffffu, s, o);
    if ((threadIdx.x & 31) == 0) sm[threadIdx.x >> 5] = s;
    __syncthreads();
    if (threadIdx.x < 32) {
        float v = (threadIdx.x < (blockDim.x >> 5)) ? sm[threadIdx.x] : 0.0f;
        #pragma unroll
        for (int o = 16; o > 0; o >>= 1) v += __shfl_down_sync(0xffffffffu, v, o);
        if (threadIdx.x == 0) g_bias[b] = fmaxf(v * (1.0f / (float)HW), 0.0f);
    }
}

// ---------------------------------------------------------------------------
// Kernel 2: main acquisition
//   one thread per (batch, pixel); loops over frames[b] (warp-uniform)
// ---------------------------------------------------------------------------
__global__ void __launch_bounds__(256)
acq_kernel(const float* __restrict__ in, const int* __restrict__ frames,
           float* __restrict__ out,
           uint32_t ku0, uint32_t ku1, uint32_t kn0, uint32_t kn1) {
    int tid = blockIdx.x * blockDim.x + threadIdx.x;
    if (tid >= NPIX) return;
    int b = tid >> 18;            // HW = 2^18
    int p = tid & (HW - 1);

    const float* base = in + (size_t)b * Cn * HW + p;
    float img = base[0];
    float fw  = fmaxf(base[2 * HW], 0.0f);
    float fa  = fmaxf(base[3 * HW], 0.0f);
    float gw  = fmaxf(base[4 * HW], 0.0f);
    float bias = g_bias[b];
    int   nf  = frames[b];

    float cb = img + bias;

    // center = clip(cb + fw * (1/(fa+1))^fa, 0, 1)   (accurate powf: once/pixel)
    float center = cb + fw * powf(1.0f / (fa + 1.0f), fa);
    center = fminf(fmaxf(center, 0.0f), 1.0f);

    const float LO = -0.99999994f;       // nextafter(-1, 0) in f32
    float acc = 0.0f;
    uint32_t jbase = (uint32_t)(b * FMAX) * (uint32_t)HW + (uint32_t)p;

    for (int f = 0; f < nf; ++f) {
        uint32_t j = jbase + (uint32_t)f * (uint32_t)HW;

        uint32_t ub, nb;
#if RNG_PARTITIONABLE
        { uint32_t a0, a1; tf2x32(ku0, ku1, 0u, j, a0, a1); ub = a0 ^ a1; }
        { uint32_t a0, a1; tf2x32(kn0, kn1, 0u, j, a0, a1); nb = a0 ^ a1; }
#else
        if (j < HALF) {
            uint32_t a0, a1; tf2x32(ku0, ku1, j, j + HALF, a0, a1); ub = a0;
            uint32_t b0, b1; tf2x32(kn0, kn1, j, j + HALF, b0, b1); nb = b0;
        } else {
            uint32_t a0, a1; tf2x32(ku0, ku1, j - HALF, j, a0, a1); ub = a1;
            uint32_t b0, b1; tf2x32(kn0, kn1, j - HALF, j, b0, b1); nb = b1;
        }
#endif
        // ---- uniform branch: fw * (-log u)^(-fa) ----
        float u = bits_to_unit(ub);
        u = fminf(fmaxf(u, 1e-6f), 0.999999f);       // jnp.clip(u, 1e-6, 1-1e-6)
        float t = -logf(u);                          // accurate log (rel-exact near u~1)
        // pow(t, -fa) = ex2(-fa * lg2(t)) ; MUFU abs-error is fine here
        float l2t, ex;
        asm("lg2.approx.f32 %0, %1;" : "=f"(l2t) : "f"(t));
        asm("ex2.approx.f32 %0, %1;" : "=f"(ex)  : "f"(-fa * l2t));

        // ---- normal branch: gw * sqrt(2)*erfinv(uniform(lo, 1)) ----
        float un = bits_to_unit(nb);
        float g  = fmaf(un, 2.0f, LO);               // (hi-lo) rounds to 2.0f exactly
        g = fmaxf(g, LO);
        float nrm = 1.41421356237f * erfinvf(g);

        float s = cb + fw * ex + gw * nrm;
        acc += fminf(fmaxf(s, 0.0f), 1.0f);
    }

    out[tid]         = acc / (float)nf;  // acquired
    out[NPIX + tid]  = center;           // center
}

// ---------------------------------------------------------------------------
// Host-side threefry (for deriving ku/kn from jax.random.key(42))
// ---------------------------------------------------------------------------
static inline uint32_t h_rotl(uint32_t x, int r) { return (x << r) | (x >> (32 - r)); }
static void h_tf2x32(uint32_t k0, uint32_t k1, uint32_t x0, uint32_t x1,
                     uint32_t& o0, uint32_t& o1) {
    uint32_t k2 = k0 ^ k1 ^ 0x1BD11BDAu;
    x0 += k0; x1 += k1;
#define HTFR(r) { x0 += x1; x1 = h_rotl(x1, (r)); x1 ^= x0; }
    HTFR(13) HTFR(15) HTFR(26) HTFR(6)   x0 += k1; x1 += k2 + 1u;
    HTFR(17) HTFR(29) HTFR(16) HTFR(24)  x0 += k2; x1 += k0 + 2u;
    HTFR(13) HTFR(15) HTFR(26) HTFR(6)   x0 += k0; x1 += k1 + 3u;
    HTFR(17) HTFR(29) HTFR(16) HTFR(24)  x0 += k1; x1 += k2 + 4u;
    HTFR(13) HTFR(15) HTFR(26) HTFR(6)   x0 += k2; x1 += k0 + 5u;
#undef HTFR
    o0 = x0; o1 = x1;
}

extern "C" void kernel_launch(void* const* d_in, const int* in_sizes, int n_in,
                              void* d_out, int out_size) {
    const float* inp    = (const float*)d_in[0];
    const int*   frames = (const int*)d_in[1];
    float*       out    = (float*)d_out;

    // noise_key = jax.random.key(42) -> key data (0, 42); ku, kn = split(key)
    uint32_t ku0, ku1, kn0, kn1;
#if RNG_PARTITIONABLE
    h_tf2x32(0u, 42u, 0u, 0u, ku0, ku1);
    h_tf2x32(0u, 42u, 0u, 1u, kn0, kn1);
#else
    uint32_t a0, a1, b0, b1;
    h_tf2x32(0u, 42u, 0u, 2u, a0, a1);
    h_tf2x32(0u, 42u, 1u, 3u, b0, b1);
    ku0 = a0; ku1 = b0; kn0 = a1; kn1 = b1;
#endif

    bias_kernel<<<Bn, 256>>>(inp);
    acq_kernel<<<NPIX / 256, 256>>>(inp, frames, out, ku0, ku1, kn0, kn1);
}

// round 3
// speedup vs baseline: 1.3389x; 1.3389x over previous
#include <cuda_runtime.h>
#include <cstdint>

// JAX threefry (partitionable scheme, confirmed round 1: rel_err 4.5e-8)
// Round 3: fixes R2's transposed bit->float scale constants:
//   uniform scale = 2^-23 (was wrongly 2^-24), normal scale = 2^-22 (was 2^-23)

static constexpr int Bn   = 8;
static constexpr int Cn   = 5;
static constexpr int FMAX = 16;
static constexpr int HW   = 512 * 512;        // 262144 = 2^18
static constexpr int NPIX = Bn * HW;          // 2097152

__device__ float g_bias[Bn];
__device__ float g_part[256];

// ---------------------------------------------------------------------------
// MUFU helpers
// ---------------------------------------------------------------------------
__device__ __forceinline__ float f_lg2(float x) { float r; asm("lg2.approx.f32 %0,%1;"  : "=f"(r) : "f"(x)); return r; }
__device__ __forceinline__ float f_ex2(float x) { float r; asm("ex2.approx.f32 %0,%1;"  : "=f"(r) : "f"(x)); return r; }
__device__ __forceinline__ float f_sqa(float x) { float r; asm("sqrt.approx.f32 %0,%1;" : "=f"(r) : "f"(x)); return r; }

// ---------------------------------------------------------------------------
// Threefry-2x32, 20 rounds; counter (0, j); returns o0 ^ o1 (partitionable bits)
// ---------------------------------------------------------------------------
__device__ __forceinline__ uint32_t tf_xor(uint32_t k0, uint32_t k1, uint32_t j) {
    uint32_t k2 = k0 ^ k1 ^ 0x1BD11BDAu;
    uint32_t x0 = k0;          // 0 + k0
    uint32_t x1 = j + k1;
#define TFR(r) { x0 += x1; x1 = __funnelshift_l(x1, x1, (r)); x1 ^= x0; }
    TFR(13) TFR(15) TFR(26) TFR(6)   x0 += k1; x1 += k2 + 1u;
    TFR(17) TFR(29) TFR(16) TFR(24)  x0 += k2; x1 += k0 + 2u;
    TFR(13) TFR(15) TFR(26) TFR(6)   x0 += k0; x1 += k1 + 3u;
    TFR(17) TFR(29) TFR(16) TFR(24)  x0 += k1; x1 += k2 + 4u;
    TFR(13) TFR(15) TFR(26) TFR(6)   x0 += k2; x1 += k0 + 5u;
#undef TFR
    return x0 ^ x1;
}

// ---------------------------------------------------------------------------
// Bias stage 1: 256 blocks (8 batches x 32 chunks), float4 loads
// ---------------------------------------------------------------------------
__global__ void __launch_bounds__(256) bias_partial(const float* __restrict__ in) {
    int b = blockIdx.x >> 5;
    int c = blockIdx.x & 31;
    const float4* p = reinterpret_cast<const float4*>(in + ((size_t)b * Cn + 1) * HW)
                    + (size_t)c * 2048;
    float s = 0.0f;
    for (int i = threadIdx.x; i < 2048; i += 256) {
        float4 q = p[i];
        s += (q.x + q.y) + (q.z + q.w);
    }
    __shared__ float sm[8];
    #pragma unroll
    for (int o = 16; o > 0; o >>= 1) s += __shfl_down_sync(0xffffffffu, s, o);
    if ((threadIdx.x & 31) == 0) sm[threadIdx.x >> 5] = s;
    __syncthreads();
    if (threadIdx.x == 0) {
        float t = 0.0f;
        #pragma unroll
        for (int k = 0; k < 8; k++) t += sm[k];
        g_part[blockIdx.x] = t;
    }
}

// Bias stage 2: one block, warp b reduces its 32 partials (deterministic tree)
__global__ void __launch_bounds__(256) bias_final() {
    int b = threadIdx.x >> 5, l = threadIdx.x & 31;
    float v = g_part[b * 32 + l];
    #pragma unroll
    for (int o = 16; o > 0; o >>= 1) v += __shfl_down_sync(0xffffffffu, v, o);
    if (l == 0) g_bias[b] = fmaxf(v * (1.0f / (float)HW), 0.0f);
}

// ---------------------------------------------------------------------------
// Main acquisition: one thread per (batch, pixel)
// ---------------------------------------------------------------------------
__global__ void __launch_bounds__(256)
acq_kernel(const float* __restrict__ in, const int* __restrict__ frames,
           float* __restrict__ out,
           uint32_t ku0, uint32_t ku1, uint32_t kn0, uint32_t kn1) {
    int tid = blockIdx.x * 256 + threadIdx.x;
    int b = tid >> 18;
    int p = tid & (HW - 1);

    const float* base = in + (size_t)b * Cn * HW + p;
    float img = base[0];
    float fw  = fmaxf(base[2 * HW], 0.0f);
    float fa  = fmaxf(base[3 * HW], 0.0f);
    float gw  = fmaxf(base[4 * HW], 0.0f);
    float bias = g_bias[b];
    int   nf   = frames[b];

    float cb  = img + bias;
    float nfa = -fa;
    float gs  = gw * 1.41421356237f;     // gw * sqrt(2), hoisted

    // center = clip(cb + fw * (fa+1)^(-fa), 0, 1)
    float cpw = f_ex2(nfa * f_lg2(fa + 1.0f));
    float center = fminf(fmaxf(fmaf(fw, cpw, cb), 0.0f), 1.0f);

    const float UCLIP_HI = 0.999999f;    // == float(1 - 1e-6), verified R1
    const float LO = -0.99999994f;       // nextafter(-1, 0)

    float acc = 0.0f;
    uint32_t j = (uint32_t)(b * FMAX) * (uint32_t)HW + (uint32_t)p;

    for (int f = 0; f < nf; ++f, j += (uint32_t)HW) {
        uint32_t ub = tf_xor(ku0, ku1, j);
        uint32_t nb = tf_xor(kn0, kn1, j);

        // ---- uniform branch: fw * (-log u)^(-fa) ----
        float su = (float)(ub >> 9);                       // exact integer in [0, 2^23)
        float u  = su * 1.1920928955078125e-7f;            // * 2^-23, exact
        u = fminf(fmaxf(u, 1e-6f), UCLIP_HI);
        // t = -log(u): MUFU for u < 0.875, log1p Taylor (exact v = u-1) above
        float tA = f_lg2(u) * -0.693147180559945f;
        float v  = u - 1.0f;                               // exact for u >= 0.5
        float P  = fmaf(v, 0.14285714f, -0.16666667f);
        P = fmaf(P, v, 0.20f);
        P = fmaf(P, v, -0.25f);
        P = fmaf(P, v, 0.33333333f);
        P = fmaf(P, v, -0.5f);
        P = fmaf(P, v, 1.0f);
        float tB = -(v * P);
        float t  = (u >= 0.875f) ? tB : tA;
        float pw = f_ex2(nfa * f_lg2(t));                  // t^(-fa)

        // ---- normal branch: gw * sqrt(2) * erfinv(g), g in (LO, 1) ----
        float sn = (float)(nb >> 9);
        float gx = fmaf(sn, 2.384185791015625e-7f, LO);    // * 2^-22: == fma(u01*2, LO), exact
        // Giles erfinv (== XLA ErfInv32 coefficients)
        float w  = f_lg2(fmaf(-gx, gx, 1.0f)) * -0.693147180559945f;
        float pe;
        if (w < 5.0f) {
            float z = w - 2.5f;
            pe = 2.81022636e-08f;
            pe = fmaf(pe, z, 3.43273939e-07f);
            pe = fmaf(pe, z, -3.5233877e-06f);
            pe = fmaf(pe, z, -4.39150654e-06f);
            pe = fmaf(pe, z, 0.00021858087f);
            pe = fmaf(pe, z, -0.00125372503f);
            pe = fmaf(pe, z, -0.00417768164f);
            pe = fmaf(pe, z, 0.246640727f);
            pe = fmaf(pe, z, 1.50140941f);
        } else {
            float z = f_sqa(w) - 3.0f;
            pe = -0.000200214257f;
            pe = fmaf(pe, z, 0.000100950558f);
            pe = fmaf(pe, z, 0.00134934322f);
            pe = fmaf(pe, z, -0.00367342844f);
            pe = fmaf(pe, z, 0.00573950773f);
            pe = fmaf(pe, z, -0.0076224613f);
            pe = fmaf(pe, z, 0.00943887047f);
            pe = fmaf(pe, z, 1.00167406f);
            pe = fmaf(pe, z, 2.83297682f);
        }

        float s = fmaf(fw, pw, cb);
        s = fmaf(gs, pe * gx, s);
        acc += fminf(fmaxf(s, 0.0f), 1.0f);
    }

    out[tid]        = acc / (float)nf;   // acquired
    out[NPIX + tid] = center;            // center
}

// ---------------------------------------------------------------------------
// Host-side threefry for key derivation from jax.random.key(42)
// ---------------------------------------------------------------------------
static inline uint32_t h_rotl(uint32_t x, int r) { return (x << r) | (x >> (32 - r)); }
static void h_tf2x32(uint32_t k0, uint32_t k1, uint32_t x0, uint32_t x1,
                     uint32_t& o0, uint32_t& o1) {
    uint32_t k2 = k0 ^ k1 ^ 0x1BD11BDAu;
    x0 += k0; x1 += k1;
#define HTFR(r) { x0 += x1; x1 = h_rotl(x1, (r)); x1 ^= x0; }
    HTFR(13) HTFR(15) HTFR(26) HTFR(6)   x0 += k1; x1 += k2 + 1u;
    HTFR(17) HTFR(29) HTFR(16) HTFR(24)  x0 += k2; x1 += k0 + 2u;
    HTFR(13) HTFR(15) HTFR(26) HTFR(6)   x0 += k0; x1 += k1 + 3u;
    HTFR(17) HTFR(29) HTFR(16) HTFR(24)  x0 += k1; x1 += k2 + 4u;
    HTFR(13) HTFR(15) HTFR(26) HTFR(6)   x0 += k2; x1 += k0 + 5u;
#undef HTFR
    o0 = x0; o1 = x1;
}

extern "C" void kernel_launch(void* const* d_in, const int* in_sizes, int n_in,
                              void* d_out, int out_size) {
    const float* inp    = (const float*)d_in[0];
    const int*   frames = (const int*)d_in[1];
    float*       out    = (float*)d_out;

    // ku, kn = split(key(42))  [partitionable]
    uint32_t ku0, ku1, kn0, kn1;
    h_tf2x32(0u, 42u, 0u, 0u, ku0, ku1);
    h_tf2x32(0u, 42u, 0u, 1u, kn0, kn1);

    bias_partial<<<256, 256>>>(inp);
    bias_final<<<1, 256>>>();
    acq_kernel<<<NPIX / 256, 256>>>(inp, frames, out, ku0, ku1, kn0, kn1);
}

// round 5
// speedup vs baseline: 1.8523x; 1.3834x over previous
#include <cuda_runtime.h>
#include <cstdint>

// JAX threefry (partitionable), bit-exact draws confirmed R1/R3 (rel_err 4e-8).
// R4: block-local compaction (37.5% pixels deterministic, 75% single-stream).
// R5: fix R4's double sqrt(2) on the gaussian term (n_term no longer scales).

static constexpr int Bn   = 8;
static constexpr int Cn   = 5;
static constexpr int FMAX = 16;
static constexpr int HW   = 512 * 512;        // 2^18
static constexpr int NPIX = Bn * HW;          // 2^21

__device__ float g_bias[Bn];
__device__ float g_part[2048];

// ---------------------------------------------------------------------------
__device__ __forceinline__ float f_lg2(float x) { float r; asm("lg2.approx.f32 %0,%1;"  : "=f"(r) : "f"(x)); return r; }
__device__ __forceinline__ float f_ex2(float x) { float r; asm("ex2.approx.f32 %0,%1;"  : "=f"(r) : "f"(x)); return r; }
__device__ __forceinline__ float f_sqa(float x) { float r; asm("sqrt.approx.f32 %0,%1;" : "=f"(r) : "f"(x)); return r; }
__device__ __forceinline__ float clip01(float x) { return fminf(fmaxf(x, 0.0f), 1.0f); }

// Threefry-2x32, 20 rounds; counter (0, j); returns x0 ^ x1 (partitionable fold)
__device__ __forceinline__ uint32_t tf_xor(uint32_t k0, uint32_t k1, uint32_t j) {
    uint32_t k2 = k0 ^ k1 ^ 0x1BD11BDAu;
    uint32_t x0 = k0;
    uint32_t x1 = j + k1;
#define TFR(r) { x0 += x1; x1 = __funnelshift_l(x1, x1, (r)); x1 ^= x0; }
    TFR(13) TFR(15) TFR(26) TFR(6)   x0 += k1; x1 += k2 + 1u;
    TFR(17) TFR(29) TFR(16) TFR(24)  x0 += k2; x1 += k0 + 2u;
    TFR(13) TFR(15) TFR(26) TFR(6)   x0 += k0; x1 += k1 + 3u;
    TFR(17) TFR(29) TFR(16) TFR(24)  x0 += k1; x1 += k2 + 4u;
    TFR(13) TFR(15) TFR(26) TFR(6)   x0 += k2; x1 += k0 + 5u;
#undef TFR
    return x0 ^ x1;
}

// uniform-bits -> (-log u)^(-fa)  (R3-validated arithmetic)
__device__ __forceinline__ float u_term(uint32_t ub, float nfa) {
    float su = (float)(ub >> 9);
    float u  = su * 1.1920928955078125e-7f;            // * 2^-23 exact
    u = fminf(fmaxf(u, 1e-6f), 0.999999f);
    float tA = f_lg2(u) * -0.693147180559945f;         // MUFU path
    float v  = u - 1.0f;                               // exact for u >= 0.5
    float P  = fmaf(v, 0.14285714f, -0.16666667f);
    P = fmaf(P, v, 0.20f);
    P = fmaf(P, v, -0.25f);
    P = fmaf(P, v, 0.33333333f);
    P = fmaf(P, v, -0.5f);
    P = fmaf(P, v, 1.0f);
    float tB = -(v * P);                               // log1p Taylor near 1
    float t  = (u >= 0.875f) ? tB : tA;
    return f_ex2(nfa * f_lg2(t));                      // t^(-fa)
}

// normal-bits -> erfinv(g)  via Giles / XLA ErfInv32.  NOTE: caller supplies
// the sqrt(2) factor inside vgs = gw*sqrt2 (R4 bug: it was applied twice).
__device__ __forceinline__ float n_term(uint32_t nb) {
    const float LO = -0.99999994f;                     // nextafter(-1, 0)
    float sn = (float)(nb >> 9);
    float gx = fmaf(sn, 2.384185791015625e-7f, LO);    // * 2^-22 exact
    float W  = f_lg2(fmaf(-gx, gx, 1.0f));             // lg2(1-gx^2), <= 0
    float pe;
    if (W > -7.21347520444482f) {                      // w = -ln2*W < 5
        float z = fmaf(-0.693147180559945f, W, -2.5f); // z = w - 2.5
        pe = 2.81022636e-08f;
        pe = fmaf(pe, z, 3.43273939e-07f);
        pe = fmaf(pe, z, -3.5233877e-06f);
        pe = fmaf(pe, z, -4.39150654e-06f);
        pe = fmaf(pe, z, 0.00021858087f);
        pe = fmaf(pe, z, -0.00125372503f);
        pe = fmaf(pe, z, -0.00417768164f);
        pe = fmaf(pe, z, 0.246640727f);
        pe = fmaf(pe, z, 1.50140941f);
    } else {
        float w = W * -0.693147180559945f;
        float z = f_sqa(w) - 3.0f;
        pe = -0.000200214257f;
        pe = fmaf(pe, z, 0.000100950558f);
        pe = fmaf(pe, z, 0.00134934322f);
        pe = fmaf(pe, z, -0.00367342844f);
        pe = fmaf(pe, z, 0.00573950773f);
        pe = fmaf(pe, z, -0.0076224613f);
        pe = fmaf(pe, z, 0.00943887047f);
        pe = fmaf(pe, z, 1.00167406f);
        pe = fmaf(pe, z, 2.83297682f);
    }
    return pe * gx;                                    // erfinv(gx)
}

// ---------------------------------------------------------------------------
// Bias: stage 1, 2048 blocks x 256 threads, one float4 each
// ---------------------------------------------------------------------------
__global__ void __launch_bounds__(256) bias_partial(const float* __restrict__ in) {
    int b = blockIdx.x >> 8;
    const float4* p4 = reinterpret_cast<const float4*>(in + ((size_t)b * Cn + 1) * HW);
    float4 q = p4[(blockIdx.x & 255) * 256 + threadIdx.x];
    float s = (q.x + q.y) + (q.z + q.w);
    __shared__ float sm[8];
    #pragma unroll
    for (int o = 16; o > 0; o >>= 1) s += __shfl_down_sync(0xffffffffu, s, o);
    if ((threadIdx.x & 31) == 0) sm[threadIdx.x >> 5] = s;
    __syncthreads();
    if (threadIdx.x == 0) {
        float t = 0.0f;
        #pragma unroll
        for (int k = 0; k < 8; k++) t += sm[k];
        g_part[blockIdx.x] = t;
    }
}

// Bias stage 2: one block; warp b reduces its 256 partials in fixed order
__global__ void __launch_bounds__(256) bias_final() {
    int b = threadIdx.x >> 5, l = threadIdx.x & 31;
    float v = 0.0f;
    #pragma unroll
    for (int k = 0; k < 8; k++) v += g_part[b * 256 + k * 32 + l];
    #pragma unroll
    for (int o = 16; o > 0; o >>= 1) v += __shfl_down_sync(0xffffffffu, v, o);
    if (l == 0) g_bias[b] = fmaxf(v * (1.0f / (float)HW), 0.0f);
}

// ---------------------------------------------------------------------------
// Main kernel: classify -> smem compaction -> per-category frame loops
// ---------------------------------------------------------------------------
__global__ void __launch_bounds__(256)
acq_kernel(const float* __restrict__ in, const int* __restrict__ frames,
           float* __restrict__ out,
           uint32_t ku0, uint32_t ku1, uint32_t kn0, uint32_t kn1) {
    __shared__ float4 stash[256];
    __shared__ unsigned short wl[256];
    __shared__ int segcnt[3];   // counts: [B, U, N]
    __shared__ int place[3];    // placement cursors

    const int t   = threadIdx.x;
    const int tid = blockIdx.x * 256 + t;
    const int b   = tid >> 18;
    const int p0  = (blockIdx.x * 256) & (HW - 1);     // block's pixel base within batch

    const float* base = in + (size_t)b * Cn * HW + (p0 + t);
    float img = base[0];
    float fw  = fmaxf(base[2 * HW], 0.0f);
    float fa  = fmaxf(base[3 * HW], 0.0f);
    float gw  = fmaxf(base[4 * HW], 0.0f);
    float bias = g_bias[b];
    int   nf   = frames[b];                            // uniform across block

    float cb  = img + bias;
    float nfa = -fa;
    float gs  = gw * 1.41421356237f;                   // gw * sqrt(2) (only place sqrt2 appears)

    // center (all pixels): cb + fw*(fa+1)^(-fa), clipped
    float cpw = f_ex2(nfa * f_lg2(fa + 1.0f));
    out[NPIX + tid] = clip01(fmaf(fw, cpw, cb));

    // classification
    bool needU = (fw > 0.0f) && (fa > 0.0f);
    bool needN = (gw > 0.0f);
    int  cat   = needU ? (needN ? 0 : 1) : (needN ? 2 : 3);
    // base value including the deterministic fw-term when fa == 0
    float cbase = (cat >= 2) ? (cb + ((fa == 0.0f) ? fw : 0.0f)) : cb;

    if (cat == 3) out[tid] = clip01(cbase);            // deterministic pixel: done

    stash[t] = make_float4(cbase, fw, nfa, gs);

    if (t < 3) { segcnt[t] = 0; }
    __syncthreads();

    // count per category (warp-aggregated)
    unsigned m0 = __ballot_sync(0xffffffffu, cat == 0);
    unsigned m1 = __ballot_sync(0xffffffffu, cat == 1);
    unsigned m2 = __ballot_sync(0xffffffffu, cat == 2);
    if ((t & 31) == 0) {
        if (m0) atomicAdd(&segcnt[0], __popc(m0));
        if (m1) atomicAdd(&segcnt[1], __popc(m1));
        if (m2) atomicAdd(&segcnt[2], __popc(m2));
    }
    __syncthreads();
    if (t == 0) {                                      // segment bases: [B | U | N]
        place[0] = 0;
        place[1] = segcnt[0];
        place[2] = segcnt[0] + segcnt[1];
    }
    __syncthreads();

    // placement (warp-aggregated per category)
    unsigned lanelt = (1u << (t & 31)) - 1u;
    if (cat == 0) {
        int ldr = __ffs(m0) - 1, bse = 0;
        if ((t & 31) == ldr) bse = atomicAdd(&place[0], __popc(m0));
        bse = __shfl_sync(m0, bse, ldr);
        wl[bse + __popc(m0 & lanelt)] = (unsigned short)t;
    } else if (cat == 1) {
        int ldr = __ffs(m1) - 1, bse = 0;
        if ((t & 31) == ldr) bse = atomicAdd(&place[1], __popc(m1));
        bse = __shfl_sync(m1, bse, ldr);
        wl[bse + __popc(m1 & lanelt)] = (unsigned short)t;
    } else if (cat == 2) {
        int ldr = __ffs(m2) - 1, bse = 0;
        if ((t & 31) == ldr) bse = atomicAdd(&place[2], __popc(m2));
        bse = __shfl_sync(m2, bse, ldr);
        wl[bse + __popc(m2 & lanelt)] = (unsigned short)t;
    }
    __syncthreads();

    const int nB = segcnt[0], nU = segcnt[1], nN = segcnt[2];
    const int total = nB + nU + nN;
    if (t >= total) return;

    int lp = wl[t];
    float4 v = stash[lp];
    float vb = v.x, vfw = v.y, vnfa = v.z, vgs = v.w;

    uint32_t j = (uint32_t)(b * FMAX) * (uint32_t)HW + (uint32_t)(p0 + lp);
    float acc = 0.0f;

    if (t < nB) {
        // both streams
        for (int f = 0; f < nf; ++f, j += (uint32_t)HW) {
            uint32_t ub = tf_xor(ku0, ku1, j);
            uint32_t nb = tf_xor(kn0, kn1, j);
            float s = fmaf(vfw, u_term(ub, vnfa), vb);
            s = fmaf(vgs, n_term(nb), s);
            acc += clip01(s);
        }
    } else if (t < nB + nU) {
        // uniform-only, 2-way unrolled for threefry-chain ILP
        int f = 0;
        for (; f + 2 <= nf; f += 2, j += 2u * (uint32_t)HW) {
            uint32_t u0 = tf_xor(ku0, ku1, j);
            uint32_t u1 = tf_xor(ku0, ku1, j + (uint32_t)HW);
            acc += clip01(fmaf(vfw, u_term(u0, vnfa), vb));
            acc += clip01(fmaf(vfw, u_term(u1, vnfa), vb));
        }
        if (f < nf) {
            uint32_t u0 = tf_xor(ku0, ku1, j);
            acc += clip01(fmaf(vfw, u_term(u0, vnfa), vb));
        }
    } else {
        // normal-only, 2-way unrolled
        int f = 0;
        for (; f + 2 <= nf; f += 2, j += 2u * (uint32_t)HW) {
            uint32_t n0 = tf_xor(kn0, kn1, j);
            uint32_t n1 = tf_xor(kn0, kn1, j + (uint32_t)HW);
            acc += clip01(fmaf(vgs, n_term(n0), vb));
            acc += clip01(fmaf(vgs, n_term(n1), vb));
        }
        if (f < nf) {
            uint32_t n0 = tf_xor(kn0, kn1, j);
            acc += clip01(fmaf(vgs, n_term(n0), vb));
        }
    }

    out[blockIdx.x * 256 + lp] = acc / (float)nf;
}

// ---------------------------------------------------------------------------
// Host-side threefry for key derivation from jax.random.key(42)
// ---------------------------------------------------------------------------
static inline uint32_t h_rotl(uint32_t x, int r) { return (x << r) | (x >> (32 - r)); }
static void h_tf2x32(uint32_t k0, uint32_t k1, uint32_t x0, uint32_t x1,
                     uint32_t& o0, uint32_t& o1) {
    uint32_t k2 = k0 ^ k1 ^ 0x1BD11BDAu;
    x0 += k0; x1 += k1;
#define HTFR(r) { x0 += x1; x1 = h_rotl(x1, (r)); x1 ^= x0; }
    HTFR(13) HTFR(15) HTFR(26) HTFR(6)   x0 += k1; x1 += k2 + 1u;
    HTFR(17) HTFR(29) HTFR(16) HTFR(24)  x0 += k2; x1 += k0 + 2u;
    HTFR(13) HTFR(15) HTFR(26) HTFR(6)   x0 += k0; x1 += k1 + 3u;
    HTFR(17) HTFR(29) HTFR(16) HTFR(24)  x0 += k1; x1 += k2 + 4u;
    HTFR(13) HTFR(15) HTFR(26) HTFR(6)   x0 += k2; x1 += k0 + 5u;
#undef HTFR
    o0 = x0; o1 = x1;
}

extern "C" void kernel_launch(void* const* d_in, const int* in_sizes, int n_in,
                              void* d_out, int out_size) {
    const float* inp    = (const float*)d_in[0];
    const int*   frames = (const int*)d_in[1];
    float*       out    = (float*)d_out;

    uint32_t ku0, ku1, kn0, kn1;
    h_tf2x32(0u, 42u, 0u, 0u, ku0, ku1);
    h_tf2x32(0u, 42u, 0u, 1u, kn0, kn1);

    bias_partial<<<2048, 256>>>(inp);
    bias_final<<<1, 256>>>();
    acq_kernel<<<NPIX / 256, 256>>>(inp, frames, out, ku0, ku1, kn0, kn1);
}

// round 6
// speedup vs baseline: 1.8789x; 1.0144x over previous
#include <cuda_runtime.h>
#include <cstdint>

// JAX threefry (partitionable), bit-exact draws confirmed (rel_err ~5e-8).
// R5: block-local compaction validated (117.2us).
// R6: batch-interleaved block remap (wave-tail balance), B-loop 2x unroll
//     (4 threefry chains in flight), bias stage MLP=4.

static constexpr int Bn   = 8;
static constexpr int Cn   = 5;
static constexpr int FMAX = 16;
static constexpr int HW   = 512 * 512;        // 2^18
static constexpr int NPIX = Bn * HW;          // 2^21

__device__ float g_bias[Bn];
__device__ float g_part[512];

// ---------------------------------------------------------------------------
__device__ __forceinline__ float f_lg2(float x) { float r; asm("lg2.approx.f32 %0,%1;"  : "=f"(r) : "f"(x)); return r; }
__device__ __forceinline__ float f_ex2(float x) { float r; asm("ex2.approx.f32 %0,%1;"  : "=f"(r) : "f"(x)); return r; }
__device__ __forceinline__ float f_sqa(float x) { float r; asm("sqrt.approx.f32 %0,%1;" : "=f"(r) : "f"(x)); return r; }
__device__ __forceinline__ float clip01(float x) { return fminf(fmaxf(x, 0.0f), 1.0f); }

// Threefry-2x32, 20 rounds; counter (0, j); returns x0 ^ x1 (partitionable fold)
__device__ __forceinline__ uint32_t tf_xor(uint32_t k0, uint32_t k1, uint32_t j) {
    uint32_t k2 = k0 ^ k1 ^ 0x1BD11BDAu;
    uint32_t x0 = k0;
    uint32_t x1 = j + k1;
#define TFR(r) { x0 += x1; x1 = __funnelshift_l(x1, x1, (r)); x1 ^= x0; }
    TFR(13) TFR(15) TFR(26) TFR(6)   x0 += k1; x1 += k2 + 1u;
    TFR(17) TFR(29) TFR(16) TFR(24)  x0 += k2; x1 += k0 + 2u;
    TFR(13) TFR(15) TFR(26) TFR(6)   x0 += k0; x1 += k1 + 3u;
    TFR(17) TFR(29) TFR(16) TFR(24)  x0 += k1; x1 += k2 + 4u;
    TFR(13) TFR(15) TFR(26) TFR(6)   x0 += k2; x1 += k0 + 5u;
#undef TFR
    return x0 ^ x1;
}

// uniform-bits -> (-log u)^(-fa)  (bit-validated R3/R5)
__device__ __forceinline__ float u_term(uint32_t ub, float nfa) {
    float su = (float)(ub >> 9);
    float u  = su * 1.1920928955078125e-7f;            // * 2^-23 exact
    u = fminf(fmaxf(u, 1e-6f), 0.999999f);
    float tA = f_lg2(u) * -0.693147180559945f;         // MUFU path
    float v  = u - 1.0f;                               // exact for u >= 0.5
    float P  = fmaf(v, 0.14285714f, -0.16666667f);
    P = fmaf(P, v, 0.20f);
    P = fmaf(P, v, -0.25f);
    P = fmaf(P, v, 0.33333333f);
    P = fmaf(P, v, -0.5f);
    P = fmaf(P, v, 1.0f);
    float tB = -(v * P);                               // log1p Taylor near 1
    float t  = (u >= 0.875f) ? tB : tA;
    return f_ex2(nfa * f_lg2(t));                      // t^(-fa)
}

// normal-bits -> erfinv(g); caller supplies sqrt(2) inside vgs = gw*sqrt2
__device__ __forceinline__ float n_term(uint32_t nb) {
    const float LO = -0.99999994f;                     // nextafter(-1, 0)
    float sn = (float)(nb >> 9);
    float gx = fmaf(sn, 2.384185791015625e-7f, LO);    // * 2^-22 exact
    float W  = f_lg2(fmaf(-gx, gx, 1.0f));             // lg2(1-gx^2), <= 0
    float pe;
    if (W > -7.21347520444482f) {                      // w = -ln2*W < 5
        float z = fmaf(-0.693147180559945f, W, -2.5f); // z = w - 2.5
        pe = 2.81022636e-08f;
        pe = fmaf(pe, z, 3.43273939e-07f);
        pe = fmaf(pe, z, -3.5233877e-06f);
        pe = fmaf(pe, z, -4.39150654e-06f);
        pe = fmaf(pe, z, 0.00021858087f);
        pe = fmaf(pe, z, -0.00125372503f);
        pe = fmaf(pe, z, -0.00417768164f);
        pe = fmaf(pe, z, 0.246640727f);
        pe = fmaf(pe, z, 1.50140941f);
    } else {
        float w = W * -0.693147180559945f;
        float z = f_sqa(w) - 3.0f;
        pe = -0.000200214257f;
        pe = fmaf(pe, z, 0.000100950558f);
        pe = fmaf(pe, z, 0.00134934322f);
        pe = fmaf(pe, z, -0.00367342844f);
        pe = fmaf(pe, z, 0.00573950773f);
        pe = fmaf(pe, z, -0.0076224613f);
        pe = fmaf(pe, z, 0.00943887047f);
        pe = fmaf(pe, z, 1.00167406f);
        pe = fmaf(pe, z, 2.83297682f);
    }
    return pe * gx;                                    // erfinv(gx)
}

// ---------------------------------------------------------------------------
// Bias stage 1: 512 blocks (64/batch) x 256 threads, 4 strided float4 (MLP=4)
// ---------------------------------------------------------------------------
__global__ void __launch_bounds__(256) bias_partial(const float* __restrict__ in) {
    int b     = blockIdx.x >> 6;
    int chunk = blockIdx.x & 63;
    int t     = threadIdx.x;
    const float4* p4 = reinterpret_cast<const float4*>(in + ((size_t)b * Cn + 1) * HW)
                     + (size_t)chunk * 1024;
    float4 a = p4[t], b4 = p4[t + 256], c = p4[t + 512], d = p4[t + 768];
    float s = ((a.x + a.y) + (a.z + a.w)) + ((b4.x + b4.y) + (b4.z + b4.w))
            + ((c.x + c.y) + (c.z + c.w)) + ((d.x + d.y) + (d.z + d.w));
    __shared__ float sm[8];
    #pragma unroll
    for (int o = 16; o > 0; o >>= 1) s += __shfl_down_sync(0xffffffffu, s, o);
    if ((t & 31) == 0) sm[t >> 5] = s;
    __syncthreads();
    if (t == 0) {
        float acc = 0.0f;
        #pragma unroll
        for (int k = 0; k < 8; k++) acc += sm[k];
        g_part[blockIdx.x] = acc;
    }
}

// Bias stage 2: one block; warp b reduces its 64 partials in fixed order
__global__ void __launch_bounds__(256) bias_final() {
    int b = threadIdx.x >> 5, l = threadIdx.x & 31;
    float v = g_part[b * 64 + l] + g_part[b * 64 + 32 + l];
    #pragma unroll
    for (int o = 16; o > 0; o >>= 1) v += __shfl_down_sync(0xffffffffu, v, o);
    if (l == 0) g_bias[b] = fmaxf(v * (1.0f / (float)HW), 0.0f);
}

// ---------------------------------------------------------------------------
// Main kernel: batch-interleaved blocks; classify -> smem compaction -> loops
// ---------------------------------------------------------------------------
__global__ void __launch_bounds__(256)
acq_kernel(const float* __restrict__ in, const int* __restrict__ frames,
           float* __restrict__ out,
           uint32_t ku0, uint32_t ku1, uint32_t kn0, uint32_t kn1) {
    __shared__ float4 stash[256];
    __shared__ unsigned short wl[256];
    __shared__ int segcnt[3];   // counts: [B, U, N]
    __shared__ int place[3];    // placement cursors

    const int t     = threadIdx.x;
    const int b     = blockIdx.x & 7;              // batch-interleaved remap
    const int chunk = blockIdx.x >> 3;
    const int p0    = chunk * 256;                 // pixel base within batch
    const int gpix  = b * HW + p0;                 // global output pixel base

    const float* base = in + (size_t)b * Cn * HW + (p0 + t);
    float img = base[0];
    float fw  = fmaxf(base[2 * HW], 0.0f);
    float fa  = fmaxf(base[3 * HW], 0.0f);
    float gw  = fmaxf(base[4 * HW], 0.0f);
    float bias = g_bias[b];
    int   nf   = frames[b];                        // uniform across block

    float cb  = img + bias;
    float nfa = -fa;
    float gs  = gw * 1.41421356237f;               // gw * sqrt(2)

    // center (all pixels): cb + fw*(fa+1)^(-fa), clipped
    float cpw = f_ex2(nfa * f_lg2(fa + 1.0f));
    out[NPIX + gpix + t] = clip01(fmaf(fw, cpw, cb));

    // classification
    bool needU = (fw > 0.0f) && (fa > 0.0f);
    bool needN = (gw > 0.0f);
    int  cat   = needU ? (needN ? 0 : 1) : (needN ? 2 : 3);
    float cbase = (cat >= 2) ? (cb + ((fa == 0.0f) ? fw : 0.0f)) : cb;

    if (cat == 3) out[gpix + t] = clip01(cbase);   // deterministic pixel: done

    stash[t] = make_float4(cbase, fw, nfa, gs);

    if (t < 3) { segcnt[t] = 0; }
    __syncthreads();

    unsigned m0 = __ballot_sync(0xffffffffu, cat == 0);
    unsigned m1 = __ballot_sync(0xffffffffu, cat == 1);
    unsigned m2 = __ballot_sync(0xffffffffu, cat == 2);
    if ((t & 31) == 0) {
        if (m0) atomicAdd(&segcnt[0], __popc(m0));
        if (m1) atomicAdd(&segcnt[1], __popc(m1));
        if (m2) atomicAdd(&segcnt[2], __popc(m2));
    }
    __syncthreads();
    if (t == 0) {                                  // segment bases: [B | U | N]
        place[0] = 0;
        place[1] = segcnt[0];
        place[2] = segcnt[0] + segcnt[1];
    }
    __syncthreads();

    unsigned lanelt = (1u << (t & 31)) - 1u;
    if (cat == 0) {
        int ldr = __ffs(m0) - 1, bse = 0;
        if ((t & 31) == ldr) bse = atomicAdd(&place[0], __popc(m0));
        bse = __shfl_sync(m0, bse, ldr);
        wl[bse + __popc(m0 & lanelt)] = (unsigned short)t;
    } else if (cat == 1) {
        int ldr = __ffs(m1) - 1, bse = 0;
        if ((t & 31) == ldr) bse = atomicAdd(&place[1], __popc(m1));
        bse = __shfl_sync(m1, bse, ldr);
        wl[bse + __popc(m1 & lanelt)] = (unsigned short)t;
    } else if (cat == 2) {
        int ldr = __ffs(m2) - 1, bse = 0;
        if ((t & 31) == ldr) bse = atomicAdd(&place[2], __popc(m2));
        bse = __shfl_sync(m2, bse, ldr);
        wl[bse + __popc(m2 & lanelt)] = (unsigned short)t;
    }
    __syncthreads();

    const int nB = segcnt[0], nU = segcnt[1], nN = segcnt[2];
    const int total = nB + nU + nN;
    if (t >= total) return;

    int lp = wl[t];
    float4 v = stash[lp];
    float vb = v.x, vfw = v.y, vnfa = v.z, vgs = v.w;

    uint32_t j = (uint32_t)(b * FMAX) * (uint32_t)HW + (uint32_t)(p0 + lp);
    float acc = 0.0f;

    if (t < nB) {
        // both streams, 2-way unrolled: 4 independent threefry chains
        int f = 0;
        for (; f + 2 <= nf; f += 2, j += 2u * (uint32_t)HW) {
            uint32_t ub0 = tf_xor(ku0, ku1, j);
            uint32_t nb0 = tf_xor(kn0, kn1, j);
            uint32_t ub1 = tf_xor(ku0, ku1, j + (uint32_t)HW);
            uint32_t nb1 = tf_xor(kn0, kn1, j + (uint32_t)HW);
            float s0 = fmaf(vfw, u_term(ub0, vnfa), vb);
            s0 = fmaf(vgs, n_term(nb0), s0);
            float s1 = fmaf(vfw, u_term(ub1, vnfa), vb);
            s1 = fmaf(vgs, n_term(nb1), s1);
            acc += clip01(s0);
            acc += clip01(s1);
        }
        if (f < nf) {
            uint32_t ub0 = tf_xor(ku0, ku1, j);
            uint32_t nb0 = tf_xor(kn0, kn1, j);
            float s0 = fmaf(vfw, u_term(ub0, vnfa), vb);
            s0 = fmaf(vgs, n_term(nb0), s0);
            acc += clip01(s0);
        }
    } else if (t < nB + nU) {
        // uniform-only, 2-way unrolled
        int f = 0;
        for (; f + 2 <= nf; f += 2, j += 2u * (uint32_t)HW) {
            uint32_t u0 = tf_xor(ku0, ku1, j);
            uint32_t u1 = tf_xor(ku0, ku1, j + (uint32_t)HW);
            acc += clip01(fmaf(vfw, u_term(u0, vnfa), vb));
            acc += clip01(fmaf(vfw, u_term(u1, vnfa), vb));
        }
        if (f < nf) {
            uint32_t u0 = tf_xor(ku0, ku1, j);
            acc += clip01(fmaf(vfw, u_term(u0, vnfa), vb));
        }
    } else {
        // normal-only, 2-way unrolled
        int f = 0;
        for (; f + 2 <= nf; f += 2, j += 2u * (uint32_t)HW) {
            uint32_t n0 = tf_xor(kn0, kn1, j);
            uint32_t n1 = tf_xor(kn0, kn1, j + (uint32_t)HW);
            acc += clip01(fmaf(vgs, n_term(n0), vb));
            acc += clip01(fmaf(vgs, n_term(n1), vb));
        }
        if (f < nf) {
            uint32_t n0 = tf_xor(kn0, kn1, j);
            acc += clip01(fmaf(vgs, n_term(n0), vb));
        }
    }

    out[gpix + lp] = acc / (float)nf;
}

// ---------------------------------------------------------------------------
// Host-side threefry for key derivation from jax.random.key(42)
// ---------------------------------------------------------------------------
static inline uint32_t h_rotl(uint32_t x, int r) { return (x << r) | (x >> (32 - r)); }
static void h_tf2x32(uint32_t k0, uint32_t k1, uint32_t x0, uint32_t x1,
                     uint32_t& o0, uint32_t& o1) {
    uint32_t k2 = k0 ^ k1 ^ 0x1BD11BDAu;
    x0 += k0; x1 += k1;
#define HTFR(r) { x0 += x1; x1 = h_rotl(x1, (r)); x1 ^= x0; }
    HTFR(13) HTFR(15) HTFR(26) HTFR(6)   x0 += k1; x1 += k2 + 1u;
    HTFR(17) HTFR(29) HTFR(16) HTFR(24)  x0 += k2; x1 += k0 + 2u;
    HTFR(13) HTFR(15) HTFR(26) HTFR(6)   x0 += k0; x1 += k1 + 3u;
    HTFR(17) HTFR(29) HTFR(16) HTFR(24)  x0 += k1; x1 += k2 + 4u;
    HTFR(13) HTFR(15) HTFR(26) HTFR(6)   x0 += k2; x1 += k0 + 5u;
#undef HTFR
    o0 = x0; o1 = x1;
}

extern "C" void kernel_launch(void* const* d_in, const int* in_sizes, int n_in,
                              void* d_out, int out_size) {
    const float* inp    = (const float*)d_in[0];
    const int*   frames = (const int*)d_in[1];
    float*       out    = (float*)d_out;

    uint32_t ku0, ku1, kn0, kn1;
    h_tf2x32(0u, 42u, 0u, 0u, ku0, ku1);
    h_tf2x32(0u, 42u, 0u, 1u, kn0, kn1);

    bias_partial<<<512, 256>>>(inp);
    bias_final<<<1, 256>>>();
    acq_kernel<<<NPIX / 256, 256>>>(inp, frames, out, ku0, ku1, kn0, kn1);
}

// round 7
// speedup vs baseline: 1.9145x; 1.0189x over previous
#include <cuda_runtime.h>
#include <cstdint>

// JAX threefry (partitionable), bit-exact draws confirmed (rel_err ~5e-8).
// R5: block-local compaction (117.2us). R6: remap/unroll (115.5us, neutral).
// R7: balanced worklist — cat0 pixels split into two half-frame-range entries
//     so EVERY entry does ~nf threefry calls; removes the 2x B-warp block tail.

static constexpr int Bn   = 8;
static constexpr int Cn   = 5;
static constexpr int FMAX = 16;
static constexpr int HW   = 512 * 512;        // 2^18
static constexpr int NPIX = Bn * HW;          // 2^21

__device__ float g_bias[Bn];
__device__ float g_part[512];

// ---------------------------------------------------------------------------
__device__ __forceinline__ float f_lg2(float x) { float r; asm("lg2.approx.f32 %0,%1;"  : "=f"(r) : "f"(x)); return r; }
__device__ __forceinline__ float f_ex2(float x) { float r; asm("ex2.approx.f32 %0,%1;"  : "=f"(r) : "f"(x)); return r; }
__device__ __forceinline__ float f_sqa(float x) { float r; asm("sqrt.approx.f32 %0,%1;" : "=f"(r) : "f"(x)); return r; }
__device__ __forceinline__ float clip01(float x) { return fminf(fmaxf(x, 0.0f), 1.0f); }

// Threefry-2x32, 20 rounds; counter (0, j); returns x0 ^ x1 (partitionable fold)
__device__ __forceinline__ uint32_t tf_xor(uint32_t k0, uint32_t k1, uint32_t j) {
    uint32_t k2 = k0 ^ k1 ^ 0x1BD11BDAu;
    uint32_t x0 = k0;
    uint32_t x1 = j + k1;
#define TFR(r) { x0 += x1; x1 = __funnelshift_l(x1, x1, (r)); x1 ^= x0; }
    TFR(13) TFR(15) TFR(26) TFR(6)   x0 += k1; x1 += k2 + 1u;
    TFR(17) TFR(29) TFR(16) TFR(24)  x0 += k2; x1 += k0 + 2u;
    TFR(13) TFR(15) TFR(26) TFR(6)   x0 += k0; x1 += k1 + 3u;
    TFR(17) TFR(29) TFR(16) TFR(24)  x0 += k1; x1 += k2 + 4u;
    TFR(13) TFR(15) TFR(26) TFR(6)   x0 += k2; x1 += k0 + 5u;
#undef TFR
    return x0 ^ x1;
}

// uniform-bits -> (-log u)^(-fa)  (bit-validated R3/R5)
__device__ __forceinline__ float u_term(uint32_t ub, float nfa) {
    float su = (float)(ub >> 9);
    float u  = su * 1.1920928955078125e-7f;            // * 2^-23 exact
    u = fminf(fmaxf(u, 1e-6f), 0.999999f);
    float tA = f_lg2(u) * -0.693147180559945f;         // MUFU path
    float v  = u - 1.0f;                               // exact for u >= 0.5
    float P  = fmaf(v, 0.14285714f, -0.16666667f);
    P = fmaf(P, v, 0.20f);
    P = fmaf(P, v, -0.25f);
    P = fmaf(P, v, 0.33333333f);
    P = fmaf(P, v, -0.5f);
    P = fmaf(P, v, 1.0f);
    float tB = -(v * P);                               // log1p Taylor near 1
    float t  = (u >= 0.875f) ? tB : tA;
    return f_ex2(nfa * f_lg2(t));                      // t^(-fa)
}

// normal-bits -> erfinv(g); caller supplies sqrt(2) inside vgs = gw*sqrt2
__device__ __forceinline__ float n_term(uint32_t nb) {
    const float LO = -0.99999994f;                     // nextafter(-1, 0)
    float sn = (float)(nb >> 9);
    float gx = fmaf(sn, 2.384185791015625e-7f, LO);    // * 2^-22 exact
    float W  = f_lg2(fmaf(-gx, gx, 1.0f));             // lg2(1-gx^2), <= 0
    float pe;
    if (W > -7.21347520444482f) {                      // w = -ln2*W < 5
        float z = fmaf(-0.693147180559945f, W, -2.5f); // z = w - 2.5
        pe = 2.81022636e-08f;
        pe = fmaf(pe, z, 3.43273939e-07f);
        pe = fmaf(pe, z, -3.5233877e-06f);
        pe = fmaf(pe, z, -4.39150654e-06f);
        pe = fmaf(pe, z, 0.00021858087f);
        pe = fmaf(pe, z, -0.00125372503f);
        pe = fmaf(pe, z, -0.00417768164f);
        pe = fmaf(pe, z, 0.246640727f);
        pe = fmaf(pe, z, 1.50140941f);
    } else {
        float w = W * -0.693147180559945f;
        float z = f_sqa(w) - 3.0f;
        pe = -0.000200214257f;
        pe = fmaf(pe, z, 0.000100950558f);
        pe = fmaf(pe, z, 0.00134934322f);
        pe = fmaf(pe, z, -0.00367342844f);
        pe = fmaf(pe, z, 0.00573950773f);
        pe = fmaf(pe, z, -0.0076224613f);
        pe = fmaf(pe, z, 0.00943887047f);
        pe = fmaf(pe, z, 1.00167406f);
        pe = fmaf(pe, z, 2.83297682f);
    }
    return pe * gx;                                    // erfinv(gx)
}

// ---------------------------------------------------------------------------
// Bias stage 1: 512 blocks (64/batch) x 256 threads, 4 strided float4 (MLP=4)
// ---------------------------------------------------------------------------
__global__ void __launch_bounds__(256) bias_partial(const float* __restrict__ in) {
    int b     = blockIdx.x >> 6;
    int chunk = blockIdx.x & 63;
    int t     = threadIdx.x;
    const float4* p4 = reinterpret_cast<const float4*>(in + ((size_t)b * Cn + 1) * HW)
                     + (size_t)chunk * 1024;
    float4 a = p4[t], b4 = p4[t + 256], c = p4[t + 512], d = p4[t + 768];
    float s = ((a.x + a.y) + (a.z + a.w)) + ((b4.x + b4.y) + (b4.z + b4.w))
            + ((c.x + c.y) + (c.z + c.w)) + ((d.x + d.y) + (d.z + d.w));
    __shared__ float sm[8];
    #pragma unroll
    for (int o = 16; o > 0; o >>= 1) s += __shfl_down_sync(0xffffffffu, s, o);
    if ((t & 31) == 0) sm[t >> 5] = s;
    __syncthreads();
    if (t == 0) {
        float acc = 0.0f;
        #pragma unroll
        for (int k = 0; k < 8; k++) acc += sm[k];
        g_part[blockIdx.x] = acc;
    }
}

// Bias stage 2: one block; warp b reduces its 64 partials in fixed order
__global__ void __launch_bounds__(256) bias_final() {
    int b = threadIdx.x >> 5, l = threadIdx.x & 31;
    float v = g_part[b * 64 + l] + g_part[b * 64 + 32 + l];
    #pragma unroll
    for (int o = 16; o > 0; o >>= 1) v += __shfl_down_sync(0xffffffffu, v, o);
    if (l == 0) g_bias[b] = fmaxf(v * (1.0f / (float)HW), 0.0f);
}

// ---------------------------------------------------------------------------
// Main kernel: classify -> balanced compaction -> uniform-work frame loops
// Segments: [Blo(nB) | Bhi(nB) | U(nU) | N(nN)], Blo/Bhi are the two
// half-frame-range entries of each cat0 pixel (pair i <-> nB+i).
// ---------------------------------------------------------------------------
__global__ void __launch_bounds__(256)
acq_kernel(const float* __restrict__ in, const int* __restrict__ frames,
           float* __restrict__ out,
           uint32_t ku0, uint32_t ku1, uint32_t kn0, uint32_t kn1) {
    __shared__ float4 stash[256];
    __shared__ unsigned short wl[512];
    __shared__ float partA[256];
    __shared__ float partB[256];
    __shared__ int segcnt[3];   // [B, U, N]
    __shared__ int place[3];

    const int t     = threadIdx.x;
    const int b     = blockIdx.x & 7;              // batch-interleaved remap
    const int chunk = blockIdx.x >> 3;
    const int p0    = chunk * 256;                 // pixel base within batch
    const int gpix  = b * HW + p0;

    const float* base = in + (size_t)b * Cn * HW + (p0 + t);
    float img = base[0];
    float fw  = fmaxf(base[2 * HW], 0.0f);
    float fa  = fmaxf(base[3 * HW], 0.0f);
    float gw  = fmaxf(base[4 * HW], 0.0f);
    float bias = g_bias[b];
    const int nf = frames[b];                      // uniform across block
    const int hf = (nf + 1) >> 1;                  // frame split point

    float cb  = img + bias;
    float nfa = -fa;
    float gs  = gw * 1.41421356237f;               // gw * sqrt(2)

    // center (all pixels)
    float cpw = f_ex2(nfa * f_lg2(fa + 1.0f));
    out[NPIX + gpix + t] = clip01(fmaf(fw, cpw, cb));

    // classification
    bool needU = (fw > 0.0f) && (fa > 0.0f);
    bool needN = (gw > 0.0f);
    int  cat   = needU ? (needN ? 0 : 1) : (needN ? 2 : 3);
    float cbase = (cat >= 2) ? (cb + ((fa == 0.0f) ? fw : 0.0f)) : cb;

    if (cat == 3) out[gpix + t] = clip01(cbase);   // deterministic: done

    stash[t] = make_float4(cbase, fw, nfa, gs);

    if (t < 3) segcnt[t] = 0;
    __syncthreads();

    unsigned m0 = __ballot_sync(0xffffffffu, cat == 0);
    unsigned m1 = __ballot_sync(0xffffffffu, cat == 1);
    unsigned m2 = __ballot_sync(0xffffffffu, cat == 2);
    if ((t & 31) == 0) {
        if (m0) atomicAdd(&segcnt[0], __popc(m0));
        if (m1) atomicAdd(&segcnt[1], __popc(m1));
        if (m2) atomicAdd(&segcnt[2], __popc(m2));
    }
    __syncthreads();
    const int nB = segcnt[0], nU = segcnt[1], nN = segcnt[2];
    if (t == 0) {
        place[0] = 0;                              // Blo ranks 0..nB-1
        place[1] = 2 * nB;                         // U base
        place[2] = 2 * nB + nU;                    // N base
    }
    __syncthreads();

    unsigned lanelt = (1u << (t & 31)) - 1u;
    if (cat == 0) {
        int ldr = __ffs(m0) - 1, bse = 0;
        if ((t & 31) == ldr) bse = atomicAdd(&place[0], __popc(m0));
        bse = __shfl_sync(m0, bse, ldr);
        int r = bse + __popc(m0 & lanelt);
        wl[r]      = (unsigned short)t;            // Blo entry
        wl[nB + r] = (unsigned short)t;            // Bhi entry (pair)
    } else if (cat == 1) {
        int ldr = __ffs(m1) - 1, bse = 0;
        if ((t & 31) == ldr) bse = atomicAdd(&place[1], __popc(m1));
        bse = __shfl_sync(m1, bse, ldr);
        wl[bse + __popc(m1 & lanelt)] = (unsigned short)t;
    } else if (cat == 2) {
        int ldr = __ffs(m2) - 1, bse = 0;
        if ((t & 31) == ldr) bse = atomicAdd(&place[2], __popc(m2));
        bse = __shfl_sync(m2, bse, ldr);
        wl[bse + __popc(m2 & lanelt)] = (unsigned short)t;
    }
    __syncthreads();

    const int total = 2 * nB + nU + nN;

    // entry loop (grid-stride over block threads; one pass in practice)
    for (int e = t; e < total; e += 256) {
        int lp = wl[e];
        float4 v = stash[lp];
        float vb = v.x, vfw = v.y, vnfa = v.z, vgs = v.w;
        uint32_t jb = (uint32_t)(b * FMAX) * (uint32_t)HW + (uint32_t)(p0 + lp);
        float acc = 0.0f;

        if (e < 2 * nB) {
            // both streams over half frame range
            bool lo = (e < nB);
            int f0 = lo ? 0 : hf;
            int f1 = lo ? hf : nf;
            uint32_t j = jb + (uint32_t)f0 * (uint32_t)HW;
            int f = f0;
            for (; f + 2 <= f1; f += 2, j += 2u * (uint32_t)HW) {
                uint32_t ub0 = tf_xor(ku0, ku1, j);
                uint32_t nb0 = tf_xor(kn0, kn1, j);
                uint32_t ub1 = tf_xor(ku0, ku1, j + (uint32_t)HW);
                uint32_t nb1 = tf_xor(kn0, kn1, j + (uint32_t)HW);
                float s0 = fmaf(vfw, u_term(ub0, vnfa), vb);
                s0 = fmaf(vgs, n_term(nb0), s0);
                float s1 = fmaf(vfw, u_term(ub1, vnfa), vb);
                s1 = fmaf(vgs, n_term(nb1), s1);
                acc += clip01(s0);
                acc += clip01(s1);
            }
            if (f < f1) {
                uint32_t ub0 = tf_xor(ku0, ku1, j);
                uint32_t nb0 = tf_xor(kn0, kn1, j);
                float s0 = fmaf(vfw, u_term(ub0, vnfa), vb);
                s0 = fmaf(vgs, n_term(nb0), s0);
                acc += clip01(s0);
            }
            if (lo) partA[e] = acc; else partB[e - nB] = acc;
        } else if (e < 2 * nB + nU) {
            // uniform-only, full range, 2-way unrolled
            uint32_t j = jb;
            int f = 0;
            for (; f + 2 <= nf; f += 2, j += 2u * (uint32_t)HW) {
                uint32_t u0 = tf_xor(ku0, ku1, j);
                uint32_t u1 = tf_xor(ku0, ku1, j + (uint32_t)HW);
                acc += clip01(fmaf(vfw, u_term(u0, vnfa), vb));
                acc += clip01(fmaf(vfw, u_term(u1, vnfa), vb));
            }
            if (f < nf) {
                uint32_t u0 = tf_xor(ku0, ku1, j);
                acc += clip01(fmaf(vfw, u_term(u0, vnfa), vb));
            }
            out[gpix + lp] = acc / (float)nf;
        } else {
            // normal-only, full range, 2-way unrolled
            uint32_t j = jb;
            int f = 0;
            for (; f + 2 <= nf; f += 2, j += 2u * (uint32_t)HW) {
                uint32_t n0 = tf_xor(kn0, kn1, j);
                uint32_t n1 = tf_xor(kn0, kn1, j + (uint32_t)HW);
                acc += clip01(fmaf(vgs, n_term(n0), vb));
                acc += clip01(fmaf(vgs, n_term(n1), vb));
            }
            if (f < nf) {
                uint32_t n0 = tf_xor(kn0, kn1, j);
                acc += clip01(fmaf(vgs, n_term(n0), vb));
            }
            out[gpix + lp] = acc / (float)nf;
        }
    }

    __syncthreads();

    // combine the split pairs
    for (int i = t; i < nB; i += 256) {
        int lp = wl[i];
        out[gpix + lp] = (partA[i] + partB[i]) / (float)nf;
    }
}

// ---------------------------------------------------------------------------
// Host-side threefry for key derivation from jax.random.key(42)
// ---------------------------------------------------------------------------
static inline uint32_t h_rotl(uint32_t x, int r) { return (x << r) | (x >> (32 - r)); }
static void h_tf2x32(uint32_t k0, uint32_t k1, uint32_t x0, uint32_t x1,
                     uint32_t& o0, uint32_t& o1) {
    uint32_t k2 = k0 ^ k1 ^ 0x1BD11BDAu;
    x0 += k0; x1 += k1;
#define HTFR(r) { x0 += x1; x1 = h_rotl(x1, (r)); x1 ^= x0; }
    HTFR(13) HTFR(15) HTFR(26) HTFR(6)   x0 += k1; x1 += k2 + 1u;
    HTFR(17) HTFR(29) HTFR(16) HTFR(24)  x0 += k2; x1 += k0 + 2u;
    HTFR(13) HTFR(15) HTFR(26) HTFR(6)   x0 += k0; x1 += k1 + 3u;
    HTFR(17) HTFR(29) HTFR(16) HTFR(24)  x0 += k1; x1 += k2 + 4u;
    HTFR(13) HTFR(15) HTFR(26) HTFR(6)   x0 += k2; x1 += k0 + 5u;
#undef HTFR
    o0 = x0; o1 = x1;
}

extern "C" void kernel_launch(void* const* d_in, const int* in_sizes, int n_in,
                              void* d_out, int out_size) {
    const float* inp    = (const float*)d_in[0];
    const int*   frames = (const int*)d_in[1];
    float*       out    = (float*)d_out;

    uint32_t ku0, ku1, kn0, kn1;
    h_tf2x32(0u, 42u, 0u, 0u, ku0, ku1);
    h_tf2x32(0u, 42u, 0u, 1u, kn0, kn1);

    bias_partial<<<512, 256>>>(inp);
    bias_final<<<1, 256>>>();
    acq_kernel<<<NPIX / 256, 256>>>(inp, frames, out, ku0, ku1, kn0, kn1);
}